// round 17
// baseline (speedup 1.0000x reference)
#include <cuda_runtime.h>
#include <cstdint>
#include <math.h>

// RZ gate dense matrix, N=12 (confirmed model):
//   output = 16,777,216 float32 (67 MB) = real part of the 4096x4096
//   complex64 matrix; zeros except out[4097*k] = cos(theta/2), k=0..4095.
//   theta = float32 at d_in[0].
//
// Measured walls: SM stores ~5.0 TB/s (L2 write cap); linear memset(0)
// ~6.7 TB/s (optimized zero-fill); concurrent CE+SM shares the wall.
// This round: 4 concurrent memset nodes on 4 streams over disjoint quarters
// (engage multiple copy engines), each followed on its own stream by a tiny
// diag kernel for just that quarter -> diag work overlaps other branches'
// fills instead of serializing after the full clear.

static constexpr long long DIM = 4096;
static constexpr long long DSTRIDE = DIM + 1;     // 4097 floats
static constexpr int NBRANCH = 4;
static constexpr int BLOCK = 128;

__global__ void rz_diag_range_kernel(const float* __restrict__ theta_p,
                                     float* __restrict__ outf,
                                     long long k0, long long k1,
                                     long long nfloats) {
    long long k = k0 + (long long)blockIdx.x * BLOCK + threadIdx.x;
    if (k >= k1) return;
    long long fidx = k * DSTRIDE;
    if (fidx >= nfloats) return;

    float theta = theta_p ? theta_p[0] : 0.f;
    if (!isfinite(theta)) theta = 0.f;
    outf[fidx] = cosf(0.5f * theta);
}

extern "C" void kernel_launch(void* const* d_in, const int* in_sizes, int n_in,
                              void* d_out, int out_size) {
    const float* theta = (n_in >= 1) ? (const float*)d_in[0] : nullptr;
    float* outf = (float*)d_out;
    long long nfloats = (long long)out_size;      // buffer = out_size*4 bytes

    static cudaStream_t ss[NBRANCH] = {nullptr, nullptr, nullptr, nullptr};
    static cudaEvent_t ev_fork = nullptr;
    static cudaEvent_t ev_done[NBRANCH] = {nullptr, nullptr, nullptr, nullptr};
    if (!ss[1]) {
        for (int i = 1; i < NBRANCH; ++i)
            cudaStreamCreateWithFlags(&ss[i], cudaStreamNonBlocking);
        cudaEventCreateWithFlags(&ev_fork, cudaEventDisableTiming);
        for (int i = 0; i < NBRANCH; ++i)
            cudaEventCreateWithFlags(&ev_done[i], cudaEventDisableTiming);
    }

    // Quarter boundaries in floats (multiples of 4 for clean byte ranges).
    long long q = (nfloats / NBRANCH) & ~3LL;
    long long base[NBRANCH + 1];
    for (int i = 0; i < NBRANCH; ++i) base[i] = q * i;
    base[NBRANCH] = nfloats;

    // Fork.
    cudaEventRecord(ev_fork, 0);
    for (int i = 1; i < NBRANCH; ++i)
        cudaStreamWaitEvent(ss[i], ev_fork, 0);

    for (int i = 0; i < NBRANCH; ++i) {
        cudaStream_t st = (i == 0) ? (cudaStream_t)0 : ss[i];
        long long lo = base[i], hi = base[i + 1];
        if (hi <= lo) continue;

        // Zero this quarter (independent memset node -> its own engine).
        cudaMemsetAsync((char*)d_out + lo * 4, 0, (size_t)(hi - lo) * 4, st);

        // Diagonal entries whose fidx falls in [lo, hi), after this quarter's
        // clear only; overlaps the other branches' fills.
        long long k0 = (lo + DSTRIDE - 1) / DSTRIDE;
        long long k1 = (hi + DSTRIDE - 1) / DSTRIDE;   // first k with fidx >= hi
        if (k1 > DIM) k1 = DIM;
        if (k1 > k0) {
            int grid = (int)((k1 - k0 + BLOCK - 1) / BLOCK);
            rz_diag_range_kernel<<<grid, BLOCK, 0, st>>>(theta, outf,
                                                         k0, k1, nfloats);
        }
    }

    // Join: stream 0 waits on branches 1..3.
    for (int i = 1; i < NBRANCH; ++i) {
        cudaEventRecord(ev_done[i], ss[i]);
        cudaStreamWaitEvent(0, ev_done[i], 0);
    }
}